// round 1
// baseline (speedup 1.0000x reference)
#include <cuda_runtime.h>

#define NUM_EXPERTS 8
#define AUX_COEF 0.02f

// Scratch accumulators (allocation-free per harness rules)
__device__ float g_sum_prob[NUM_EXPERTS];
__device__ float g_cnt[NUM_EXPERTS];

__global__ void router_init_kernel() {
    if (threadIdx.x < NUM_EXPERTS) {
        g_sum_prob[threadIdx.x] = 0.0f;
        g_cnt[threadIdx.x] = 0.0f;
    }
}

__global__ void __launch_bounds__(256) router_main_kernel(
    const float4* __restrict__ in, int num_tokens)
{
    const int tid    = blockIdx.x * blockDim.x + threadIdx.x;
    const int stride = gridDim.x * blockDim.x;

    float sp[NUM_EXPERTS];
    float ct[NUM_EXPERTS];
#pragma unroll
    for (int e = 0; e < NUM_EXPERTS; e++) { sp[e] = 0.0f; ct[e] = 0.0f; }

    for (int t = tid; t < num_tokens; t += stride) {
        // one token row = 32 contiguous bytes: two float4 loads
        float4 a = in[2 * t];
        float4 b = in[2 * t + 1];
        float x[NUM_EXPERTS] = {a.x, a.y, a.z, a.w, b.x, b.y, b.z, b.w};

        // softmax without max-subtraction: logits ~ N(0,1), |x| << 88, no overflow
        float ex[NUM_EXPERTS];
        float s = 0.0f;
#pragma unroll
        for (int e = 0; e < NUM_EXPERTS; e++) {
            ex[e] = __expf(x[e]);
            s += ex[e];
        }
        float inv = __frcp_rn(s);
#pragma unroll
        for (int e = 0; e < NUM_EXPERTS; e++)
            sp[e] = fmaf(ex[e], inv, sp[e]);

        // top-2 indices on logits (softmax is monotone).
        // Ascending scan with strict > matches jax.lax.top_k lowest-index tie-break.
        int i1 = 0;
        float m1 = x[0];
#pragma unroll
        for (int e = 1; e < NUM_EXPERTS; e++) {
            if (x[e] > m1) { m1 = x[e]; i1 = e; }
        }
        int i2 = (i1 == 0) ? 1 : 0;
        float m2 = x[i2];
#pragma unroll
        for (int e = 0; e < NUM_EXPERTS; e++) {
            if (e != i1 && x[e] > m2) { m2 = x[e]; i2 = e; }
        }
#pragma unroll
        for (int e = 0; e < NUM_EXPERTS; e++)
            ct[e] += (e == i1 ? 1.0f : 0.0f) + (e == i2 ? 1.0f : 0.0f);
    }

    // warp reduction
#pragma unroll
    for (int e = 0; e < NUM_EXPERTS; e++) {
#pragma unroll
        for (int off = 16; off > 0; off >>= 1) {
            sp[e] += __shfl_down_sync(0xffffffffu, sp[e], off);
            ct[e] += __shfl_down_sync(0xffffffffu, ct[e], off);
        }
    }

    // block reduction in shared, then one atomic per expert per block
    __shared__ float ssp[NUM_EXPERTS];
    __shared__ float sct[NUM_EXPERTS];
    if (threadIdx.x < NUM_EXPERTS) { ssp[threadIdx.x] = 0.0f; sct[threadIdx.x] = 0.0f; }
    __syncthreads();
    if ((threadIdx.x & 31) == 0) {
#pragma unroll
        for (int e = 0; e < NUM_EXPERTS; e++) {
            atomicAdd(&ssp[e], sp[e]);
            atomicAdd(&sct[e], ct[e]);
        }
    }
    __syncthreads();
    if (threadIdx.x < NUM_EXPERTS) {
        atomicAdd(&g_sum_prob[threadIdx.x], ssp[threadIdx.x]);
        atomicAdd(&g_cnt[threadIdx.x], sct[threadIdx.x]);
    }
}

__global__ void router_final_kernel(float* __restrict__ out, int num_tokens) {
    if (threadIdx.x == 0 && blockIdx.x == 0) {
        double total = 0.0;
        for (int e = 0; e < NUM_EXPERTS; e++)
            total += (double)g_cnt[e] * (double)g_sum_prob[e];
        double T = (double)num_tokens;
        out[0] = (float)((double)AUX_COEF * (double)NUM_EXPERTS * total / (T * T));
    }
}

extern "C" void kernel_launch(void* const* d_in, const int* in_sizes, int n_in,
                              void* d_out, int out_size) {
    const float4* in = (const float4*)d_in[0];
    float* out = (float*)d_out;
    int num_tokens = in_sizes[0] / NUM_EXPERTS;

    router_init_kernel<<<1, 32>>>();
    const int threads = 256;
    const int blocks = 148 * 16;  // 2368 blocks, grid-stride covers 4.19M tokens
    router_main_kernel<<<blocks, threads>>>(in, num_tokens);
    router_final_kernel<<<1, 32>>>(out, num_tokens);
}